// round 1
// baseline (speedup 1.0000x reference)
#include <cuda_runtime.h>

#define NN   100000
#define NE   800000
#define DIN  128
#define HID  128
#define BM   64
#define SMEM_BYTES ((128*128 + 128*68)*4)

// ---------------- scratch (static device allocations are allowed) -----------
__device__ int   g_count[NN];
__device__ int   g_rowptr[NN + 1];
__device__ int   g_cursor[NN];
__device__ int   g_adj[NE];
__device__ float g_dinv[NN];
__device__ float g_hs[(size_t)NN * HID];   // (x@W1) * dinv[row]
__device__ float g_g2[NN * 2];             // (relu(agg1)@W2) * dinv[row]
__device__ int   g_bsum[128];

// ---------------- degree / CSR build ---------------------------------------
__global__ void k_zero() {
    int i = blockIdx.x * blockDim.x + threadIdx.x;
    if (i < NN) g_count[i] = 0;
}

__global__ void k_count(const int* __restrict__ dst) {
    int e = blockIdx.x * blockDim.x + threadIdx.x;
    if (e < NE) atomicAdd(&g_count[dst[e]], 1);
}

__global__ void k_scan1() {
    __shared__ int s[1024];
    int i = blockIdx.x * 1024 + threadIdx.x;
    int v = (i < NN) ? g_count[i] : 0;
    s[threadIdx.x] = v;
    __syncthreads();
    for (int off = 1; off < 1024; off <<= 1) {
        int t = (threadIdx.x >= off) ? s[threadIdx.x - off] : 0;
        __syncthreads();
        s[threadIdx.x] += t;
        __syncthreads();
    }
    if (i < NN) g_rowptr[i] = s[threadIdx.x] - v;   // block-local exclusive
    if (threadIdx.x == 1023) g_bsum[blockIdx.x] = s[1023];
}

__global__ void k_scan2(int nblk) {
    __shared__ int s[128];
    int v = (threadIdx.x < nblk) ? g_bsum[threadIdx.x] : 0;
    s[threadIdx.x] = v;
    __syncthreads();
    for (int off = 1; off < 128; off <<= 1) {
        int t = (threadIdx.x >= off) ? s[threadIdx.x - off] : 0;
        __syncthreads();
        s[threadIdx.x] += t;
        __syncthreads();
    }
    if (threadIdx.x < nblk) g_bsum[threadIdx.x] = s[threadIdx.x] - v;  // exclusive
}

__global__ void k_finalize() {
    int i = blockIdx.x * blockDim.x + threadIdx.x;
    if (i < NN) {
        int r = g_rowptr[i] + g_bsum[i >> 10];
        g_rowptr[i] = r;
        g_cursor[i] = r;
        g_dinv[i]   = rsqrtf(1.0f + (float)g_count[i]);
    }
    if (i == 0) g_rowptr[NN] = NE;
}

__global__ void k_fill(const int* __restrict__ src, const int* __restrict__ dst) {
    int e = blockIdx.x * blockDim.x + threadIdx.x;
    if (e < NE) {
        int d   = dst[e];
        int pos = atomicAdd(&g_cursor[d], 1);
        g_adj[pos] = src[e];
    }
}

// ---------------- GEMM1: hs = (x @ W1) * dinv[row] --------------------------
__global__ void k_gemm1(const float* __restrict__ x, const float* __restrict__ W1) {
    extern __shared__ float smem[];
    float* Ws = smem;                 // [128][128]
    float* Xs = smem + 128 * 128;     // transposed [k][r], row pitch 68 floats
    const int tid = threadIdx.x;
    const int rb  = blockIdx.x * BM;

    float4* Ws4 = (float4*)Ws;
    const float4* W14 = (const float4*)W1;
#pragma unroll
    for (int t = 0; t < 16; t++) Ws4[tid + t * 256] = W14[tid + t * 256];

    const float4* x4 = (const float4*)x;
#pragma unroll
    for (int t = 0; t < 8; t++) {
        int idx = tid + t * 256;       // 0..2047 float4 slots
        int r   = idx >> 5;            // local row 0..63
        int kq  = idx & 31;            // float4 within row
        int row = rb + r;
        float4 v = (row < NN) ? x4[(size_t)row * 32 + kq] : make_float4(0.f, 0.f, 0.f, 0.f);
        Xs[(kq * 4 + 0) * 68 + r] = v.x;
        Xs[(kq * 4 + 1) * 68 + r] = v.y;
        Xs[(kq * 4 + 2) * 68 + r] = v.z;
        Xs[(kq * 4 + 3) * 68 + r] = v.w;
    }
    __syncthreads();

    const int cx = tid & 31;   // column quad: cols cx*4..cx*4+3
    const int ry = tid >> 5;   // row group:  rows ry*8..ry*8+7
    float acc[8][4];
#pragma unroll
    for (int j = 0; j < 8; j++)
#pragma unroll
        for (int c = 0; c < 4; c++) acc[j][c] = 0.f;

    const float4* Xs4 = (const float4*)Xs;
#pragma unroll 4
    for (int k = 0; k < 128; k++) {
        float4 w  = Ws4[k * 32 + cx];
        float4 a0 = Xs4[k * 17 + ry * 2];       // broadcast within warp
        float4 a1 = Xs4[k * 17 + ry * 2 + 1];
        float xr[8] = {a0.x, a0.y, a0.z, a0.w, a1.x, a1.y, a1.z, a1.w};
#pragma unroll
        for (int j = 0; j < 8; j++) {
            acc[j][0] = fmaf(xr[j], w.x, acc[j][0]);
            acc[j][1] = fmaf(xr[j], w.y, acc[j][1]);
            acc[j][2] = fmaf(xr[j], w.z, acc[j][2]);
            acc[j][3] = fmaf(xr[j], w.w, acc[j][3]);
        }
    }

    float4* hs4 = (float4*)g_hs;
#pragma unroll
    for (int j = 0; j < 8; j++) {
        int row = rb + ry * 8 + j;
        if (row < NN) {
            float s = g_dinv[row];
            hs4[(size_t)row * 32 + cx] =
                make_float4(acc[j][0] * s, acc[j][1] * s, acc[j][2] * s, acc[j][3] * s);
        }
    }
}

// ------ gather1 + relu + bias + fused 128x2 GEMM2 (warp per node) -----------
__global__ void k_gather1(const float* __restrict__ b1, const float* __restrict__ W2) {
    int gw   = (blockIdx.x * blockDim.x + threadIdx.x) >> 5;
    int lane = threadIdx.x & 31;
    if (gw >= NN) return;
    const float4* hs4 = (const float4*)g_hs;
    float4 acc = hs4[(size_t)gw * 32 + lane];      // self term (pre-scaled)
    int r0 = g_rowptr[gw], r1 = g_rowptr[gw + 1];
    for (int e = r0; e < r1; e++) {
        int s = g_adj[e];
        float4 v = hs4[(size_t)s * 32 + lane];
        acc.x += v.x; acc.y += v.y; acc.z += v.z; acc.w += v.w;
    }
    float di = g_dinv[gw];
    float4 b = ((const float4*)b1)[lane];
    float o0 = fmaxf(fmaf(di, acc.x, b.x), 0.f);
    float o1 = fmaxf(fmaf(di, acc.y, b.y), 0.f);
    float o2 = fmaxf(fmaf(di, acc.z, b.z), 0.f);
    float o3 = fmaxf(fmaf(di, acc.w, b.w), 0.f);

    // W2 is [128][2] row-major; this lane covers k = lane*4 .. lane*4+3
    const float4* w24 = (const float4*)W2;
    float4 wa = w24[lane * 2];        // k0j0 k0j1 k1j0 k1j1
    float4 wb = w24[lane * 2 + 1];    // k2j0 k2j1 k3j0 k3j1
    float p0 = o0 * wa.x + o1 * wa.z + o2 * wb.x + o3 * wb.z;
    float p1 = o0 * wa.y + o1 * wa.w + o2 * wb.y + o3 * wb.w;
#pragma unroll
    for (int off = 16; off; off >>= 1) {
        p0 += __shfl_xor_sync(0xffffffffu, p0, off);
        p1 += __shfl_xor_sync(0xffffffffu, p1, off);
    }
    if (lane == 0) {
        g_g2[gw * 2]     = di * p0;   // pre-scaled for layer 2
        g_g2[gw * 2 + 1] = di * p1;
    }
}

// ---------------- gather2: final [N,2] output -------------------------------
__global__ void k_gather2(float* __restrict__ out, const float* __restrict__ b2) {
    int gw   = (blockIdx.x * blockDim.x + threadIdx.x) >> 5;
    int lane = threadIdx.x & 31;
    if (gw >= NN) return;
    const float2* g2 = (const float2*)g_g2;
    float a0 = 0.f, a1 = 0.f;
    int r0 = g_rowptr[gw], r1 = g_rowptr[gw + 1];
    for (int e = r0 + lane; e < r1; e += 32) {
        float2 v = g2[g_adj[e]];
        a0 += v.x; a1 += v.y;
    }
#pragma unroll
    for (int off = 16; off; off >>= 1) {
        a0 += __shfl_xor_sync(0xffffffffu, a0, off);
        a1 += __shfl_xor_sync(0xffffffffu, a1, off);
    }
    if (lane == 0) {
        float di = g_dinv[gw];
        float2 self = g2[gw];
        ((float2*)out)[gw] =
            make_float2(fmaf(di, self.x + a0, b2[0]), fmaf(di, self.y + a1, b2[1]));
    }
}

// ---------------- launch -----------------------------------------------------
extern "C" void kernel_launch(void* const* d_in, const int* in_sizes, int n_in,
                              void* d_out, int out_size) {
    const float* x  = (const float*)d_in[0];
    const int*   ei = (const int*)d_in[1];
    const float* W1 = (const float*)d_in[2];
    const float* b1 = (const float*)d_in[3];
    const float* W2 = (const float*)d_in[4];
    const float* b2 = (const float*)d_in[5];
    const int* src = ei;          // edge_index[0]
    const int* dst = ei + NE;     // edge_index[1]

    cudaFuncSetAttribute(k_gemm1, cudaFuncAttributeMaxDynamicSharedMemorySize, SMEM_BYTES);

    k_zero   <<<(NN + 255) / 256, 256>>>();
    k_count  <<<(NE + 255) / 256, 256>>>(dst);
    k_scan1  <<<(NN + 1023) / 1024, 1024>>>();
    k_scan2  <<<1, 128>>>((NN + 1023) / 1024);
    k_finalize<<<(NN + 255) / 256, 256>>>();
    k_fill   <<<(NE + 255) / 256, 256>>>(src, dst);
    k_gemm1  <<<(NN + BM - 1) / BM, 256, SMEM_BYTES>>>(x, W1);
    k_gather1<<<(NN * 32 + 255) / 256, 256>>>(b1, W2);
    k_gather2<<<(NN * 32 + 255) / 256, 256>>>((float*)d_out, b2);
}